// round 1
// baseline (speedup 1.0000x reference)
#include <cuda_runtime.h>

// Problem constants (fixed shapes from reference: B=2, S=8, N=2048, D=3)
#define B_   2
#define S_   8
#define NPTS 2048
#define BS_  (B_ * S_)

#define THREADS        256
#define PTS_PER_BLOCK  256
#define CHUNKS         (NPTS / PTS_PER_BLOCK)   // 8

__device__ __forceinline__ float smooth_l1(float d) {
    float a = fabsf(d);
    return (a < 1.0f) ? 0.5f * a * a : a - 0.5f;
}

__global__ void init_out_kernel(float* out) {
    out[0] = 0.0f;
    out[1] = 0.0f;
}

// One block handles PTS_PER_BLOCK query points of one (b,s) set in one direction.
// blockIdx.x: chunk, blockIdx.y: bs index, blockIdx.z: direction (0: X->T, 1: T->X)
__global__ __launch_bounds__(THREADS) void chamfer_kernel(
    const float* __restrict__ X,
    const float* __restrict__ T,
    const float* __restrict__ W,
    float* __restrict__ out)
{
    __shared__ float4 sRef[NPTS];          // {x, y, z, 0.5*(x^2+y^2+z^2)}  32 KB
    __shared__ float  sRed[THREADS / 32];

    const int bs  = blockIdx.y;
    const int dir = blockIdx.z;
    const float* pred = dir ? T : X;
    const float* ref  = dir ? X : T;

    const float* refBase = ref + (size_t)bs * NPTS * 3;
    const int tid = threadIdx.x;

    // Cooperative load of the full reference set + precompute half squared norm
    for (int j = tid; j < NPTS; j += THREADS) {
        float x = refBase[j * 3 + 0];
        float y = refBase[j * 3 + 1];
        float z = refBase[j * 3 + 2];
        sRef[j] = make_float4(x, y, z, 0.5f * (x * x + y * y + z * z));
    }
    __syncthreads();

    // My query point
    const int i = blockIdx.x * PTS_PER_BLOCK + tid;
    const float* pp = pred + ((size_t)bs * NPTS + i) * 3;
    const float px = pp[0], py = pp[1], pz = pp[2];

    // argmin ||p - t||^2  ==  argmax (p.t - 0.5*||t||^2)
    // 4 independent running-max streams to break the select dependency chain.
    float b0 = -1e30f, b1 = -1e30f, b2 = -1e30f, b3 = -1e30f;
    int   i0 = 0,      i1 = 0,      i2 = 0,      i3 = 0;

    #pragma unroll 2
    for (int j = 0; j < NPTS; j += 4) {
        float4 t0 = sRef[j + 0];
        float4 t1 = sRef[j + 1];
        float4 t2 = sRef[j + 2];
        float4 t3 = sRef[j + 3];
        float s0 = fmaf(px, t0.x, fmaf(py, t0.y, fmaf(pz, t0.z, -t0.w)));
        float s1 = fmaf(px, t1.x, fmaf(py, t1.y, fmaf(pz, t1.z, -t1.w)));
        float s2 = fmaf(px, t2.x, fmaf(py, t2.y, fmaf(pz, t2.z, -t2.w)));
        float s3 = fmaf(px, t3.x, fmaf(py, t3.y, fmaf(pz, t3.z, -t3.w)));
        if (s0 > b0) { b0 = s0; i0 = j + 0; }
        if (s1 > b1) { b1 = s1; i1 = j + 1; }
        if (s2 > b2) { b2 = s2; i2 = j + 2; }
        if (s3 > b3) { b3 = s3; i3 = j + 3; }
    }
    // Merge streams
    float bb = b0; int bi = i0;
    if (b1 > bb) { bb = b1; bi = i1; }
    if (b2 > bb) { bb = b2; bi = i2; }
    if (b3 > bb) { bb = b3; bi = i3; }

    // Smooth L1 against nearest neighbor
    float4 tb = sRef[bi];
    float sum = smooth_l1(px - tb.x) + smooth_l1(py - tb.y) + smooth_l1(pz - tb.z);

    // Block reduction
    #pragma unroll
    for (int o = 16; o > 0; o >>= 1)
        sum += __shfl_down_sync(0xFFFFFFFFu, sum, o);
    if ((tid & 31) == 0) sRed[tid >> 5] = sum;
    __syncthreads();
    if (tid < 32) {
        float v = (tid < THREADS / 32) ? sRed[tid] : 0.0f;
        #pragma unroll
        for (int o = 4; o > 0; o >>= 1)
            v += __shfl_down_sync(0xFFFFFFFFu, v, o);
        if (tid == 0) {
            // tmp contribution: mean over (N, D) then * weight / B, summed into out[0]
            const float scale = 1.0f / ((float)B_ * (float)NPTS * 3.0f);
            atomicAdd(out, v * W[bs] * scale);
        }
    }
}

// Centroid loss: one block per (b,s) set.
__global__ __launch_bounds__(THREADS) void centroid_kernel(
    const float* __restrict__ X,
    const float* __restrict__ T,
    float* __restrict__ out)
{
    __shared__ float sRed[6][THREADS / 32];

    const int bs  = blockIdx.x;
    const int tid = threadIdx.x;
    const float* xb = X + (size_t)bs * NPTS * 3;
    const float* tb = T + (size_t)bs * NPTS * 3;

    float acc[6] = {0, 0, 0, 0, 0, 0};
    for (int j = tid; j < NPTS; j += THREADS) {
        acc[0] += xb[j * 3 + 0];
        acc[1] += xb[j * 3 + 1];
        acc[2] += xb[j * 3 + 2];
        acc[3] += tb[j * 3 + 0];
        acc[4] += tb[j * 3 + 1];
        acc[5] += tb[j * 3 + 2];
    }
    #pragma unroll
    for (int k = 0; k < 6; k++) {
        float v = acc[k];
        #pragma unroll
        for (int o = 16; o > 0; o >>= 1)
            v += __shfl_down_sync(0xFFFFFFFFu, v, o);
        if ((tid & 31) == 0) sRed[k][tid >> 5] = v;
    }
    __syncthreads();
    if (tid == 0) {
        float l = 0.0f;
        const float invN = 1.0f / (float)NPTS;
        #pragma unroll
        for (int k = 0; k < 3; k++) {
            float sx = 0.0f, st = 0.0f;
            #pragma unroll
            for (int w = 0; w < THREADS / 32; w++) {
                sx += sRed[k][w];
                st += sRed[k + 3][w];
            }
            l += smooth_l1(sx * invN - st * invN);
        }
        atomicAdd(out + 1, l * (1.0f / ((float)B_ * 3.0f)));
    }
}

extern "C" void kernel_launch(void* const* d_in, const int* in_sizes, int n_in,
                              void* d_out, int out_size) {
    const float* X = (const float*)d_in[0];   // [B,S,N,3]
    const float* T = (const float*)d_in[1];   // [B,S,N,3]
    const float* W = (const float*)d_in[2];   // [B,S]
    float* out = (float*)d_out;               // [2] -> (loss, lossc)

    init_out_kernel<<<1, 1>>>(out);

    dim3 grid(CHUNKS, BS_, 2);
    chamfer_kernel<<<grid, THREADS>>>(X, T, W, out);

    centroid_kernel<<<BS_, THREADS>>>(X, T, out);
}

// round 2
// speedup vs baseline: 1.0856x; 1.0856x over previous
#include <cuda_runtime.h>

// Shapes fixed by the problem: B=2, S=8, N=2048, D=3
#define NPTS   2048
#define BS_    16            // B*S
#define THREADS 128
#define PTS_PER_BLOCK 128
#define CHUNKS (NPTS / PTS_PER_BLOCK)   // 16
#define NBLK   (CHUNKS * BS_ * 2)       // 512

#define SCALE    16384.0f
#define INVSCALE (1.0f / 16384.0f)

__device__ float g_part[NBLK];
__device__ float g_cent[NBLK][3];

__device__ __forceinline__ float smooth_l1(float d) {
    float a = fabsf(d);
    return (a < 1.0f) ? 0.5f * a * a : a - 0.5f;
}

// Packed 2-point score: s = px*x + py*y + pz*z + w (w = -0.5*|t|^2, all ref
// operands pre-scaled by 2^14), rounded to int32.
__device__ __forceinline__ void score2(
    unsigned long long px2, unsigned long long py2, unsigned long long pz2,
    unsigned long long x2, unsigned long long y2,
    unsigned long long z2, unsigned long long w2,
    int& s0, int& s1)
{
    asm("{\n\t"
        ".reg .b64 t;\n\t"
        ".reg .f32 lo, hi;\n\t"
        "fma.rn.f32x2 t, %2, %5, %8;\n\t"
        "fma.rn.f32x2 t, %3, %6, t;\n\t"
        "fma.rn.f32x2 t, %4, %7, t;\n\t"
        "mov.b64 {lo, hi}, t;\n\t"
        "cvt.rni.s32.f32 %0, lo;\n\t"
        "cvt.rni.s32.f32 %1, hi;\n\t"
        "}"
        : "=r"(s0), "=r"(s1)
        : "l"(px2), "l"(py2), "l"(pz2), "l"(x2), "l"(y2), "l"(z2), "l"(w2));
}

__device__ __forceinline__ unsigned long long pack2(float v) {
    float2 t = make_float2(v, v);
    return *reinterpret_cast<unsigned long long*>(&t);
}

// blockIdx.x: chunk, blockIdx.y: bs, blockIdx.z: dir (0: X->T, 1: T->X)
__global__ __launch_bounds__(THREADS) void chamfer_kernel(
    const float* __restrict__ X,
    const float* __restrict__ T,
    const float* __restrict__ W)
{
    __shared__ float4 sXY[NPTS / 2];   // (x0,x1,y0,y1) * SCALE        16 KB
    __shared__ float4 sZW[NPTS / 2];   // (z0,z1,w0,w1) * SCALE        16 KB
    __shared__ float  sRed[4][THREADS / 32];

    const int bs  = blockIdx.y;
    const int dir = blockIdx.z;
    const float* pred = dir ? T : X;
    const float* ref  = dir ? X : T;
    const float* refBase = ref + (size_t)bs * NPTS * 3;
    const int tid = threadIdx.x;

    // Load ref set into smem as packed pairs, pre-scaled.
    for (int t = tid; t < NPTS / 2; t += THREADS) {
        const float* q = refBase + 6 * t;
        float x0 = q[0], y0 = q[1], z0 = q[2];
        float x1 = q[3], y1 = q[4], z1 = q[5];
        float w0 = -0.5f * (x0 * x0 + y0 * y0 + z0 * z0);
        float w1 = -0.5f * (x1 * x1 + y1 * y1 + z1 * z1);
        sXY[t] = make_float4(x0 * SCALE, x1 * SCALE, y0 * SCALE, y1 * SCALE);
        sZW[t] = make_float4(z0 * SCALE, z1 * SCALE, w0 * SCALE, w1 * SCALE);
    }
    __syncthreads();

    // My query point (unscaled).
    const int i = blockIdx.x * PTS_PER_BLOCK + tid;
    const float* pp = pred + ((size_t)bs * NPTS + i) * 3;
    const float px = pp[0], py = pp[1], pz = pp[2];
    const unsigned long long px2 = pack2(px), py2 = pack2(py), pz2 = pack2(pz);

    // argmax over key = round(s * 2^14) * 2048 + j   (4 running-max streams)
    int b0 = (int)0x80000000, b1 = b0, b2 = b0, b3 = b0;

    #pragma unroll 2
    for (int s = 0; s < NPTS / 2; s += 4) {
        ulonglong2 xyA = *reinterpret_cast<const ulonglong2*>(&sXY[s + 0]);
        ulonglong2 zwA = *reinterpret_cast<const ulonglong2*>(&sZW[s + 0]);
        ulonglong2 xyB = *reinterpret_cast<const ulonglong2*>(&sXY[s + 1]);
        ulonglong2 zwB = *reinterpret_cast<const ulonglong2*>(&sZW[s + 1]);
        ulonglong2 xyC = *reinterpret_cast<const ulonglong2*>(&sXY[s + 2]);
        ulonglong2 zwC = *reinterpret_cast<const ulonglong2*>(&sZW[s + 2]);
        ulonglong2 xyD = *reinterpret_cast<const ulonglong2*>(&sXY[s + 3]);
        ulonglong2 zwD = *reinterpret_cast<const ulonglong2*>(&sZW[s + 3]);

        int sA0, sA1, sB0, sB1, sC0, sC1, sD0, sD1;
        score2(px2, py2, pz2, xyA.x, xyA.y, zwA.x, zwA.y, sA0, sA1);
        score2(px2, py2, pz2, xyB.x, xyB.y, zwB.x, zwB.y, sB0, sB1);
        score2(px2, py2, pz2, xyC.x, xyC.y, zwC.x, zwC.y, sC0, sC1);
        score2(px2, py2, pz2, xyD.x, xyD.y, zwD.x, zwD.y, sD0, sD1);

        const int base = 2 * s;
        int k;
        k = sA0 * 2048 + (base + 0); b0 = k > b0 ? k : b0;
        k = sA1 * 2048 + (base + 1); b1 = k > b1 ? k : b1;
        k = sB0 * 2048 + (base + 2); b2 = k > b2 ? k : b2;
        k = sB1 * 2048 + (base + 3); b3 = k > b3 ? k : b3;
        k = sC0 * 2048 + (base + 4); b0 = k > b0 ? k : b0;
        k = sC1 * 2048 + (base + 5); b1 = k > b1 ? k : b1;
        k = sD0 * 2048 + (base + 6); b2 = k > b2 ? k : b2;
        k = sD1 * 2048 + (base + 7); b3 = k > b3 ? k : b3;
    }

    int best = b0;
    best = b1 > best ? b1 : best;
    best = b2 > best ? b2 : best;
    best = b3 > best ? b3 : best;

    // Decode index (low 11 bits, valid for negative keys in two's complement).
    const int bi  = best & 2047;
    const int slot = bi >> 1;
    const bool odd = bi & 1;
    float4 xy = sXY[slot];
    float4 zw = sZW[slot];
    float tx = (odd ? xy.y : xy.x) * INVSCALE;
    float ty = (odd ? xy.w : xy.z) * INVSCALE;
    float tz = (odd ? zw.y : zw.x) * INVSCALE;

    float lsum = smooth_l1(px - tx) + smooth_l1(py - ty) + smooth_l1(pz - tz);

    // Block reduction: loss sum + centroid sums of (px,py,pz).
    float v0 = lsum, v1 = px, v2 = py, v3 = pz;
    #pragma unroll
    for (int o = 16; o > 0; o >>= 1) {
        v0 += __shfl_down_sync(0xFFFFFFFFu, v0, o);
        v1 += __shfl_down_sync(0xFFFFFFFFu, v1, o);
        v2 += __shfl_down_sync(0xFFFFFFFFu, v2, o);
        v3 += __shfl_down_sync(0xFFFFFFFFu, v3, o);
    }
    if ((tid & 31) == 0) {
        sRed[0][tid >> 5] = v0;
        sRed[1][tid >> 5] = v1;
        sRed[2][tid >> 5] = v2;
        sRed[3][tid >> 5] = v3;
    }
    __syncthreads();
    if (tid == 0) {
        float t0 = 0, t1 = 0, t2 = 0, t3 = 0;
        #pragma unroll
        for (int w = 0; w < THREADS / 32; w++) {
            t0 += sRed[0][w]; t1 += sRed[1][w];
            t2 += sRed[2][w]; t3 += sRed[3][w];
        }
        const int bid = blockIdx.x + CHUNKS * bs + CHUNKS * BS_ * dir;
        g_part[bid] = t0 * W[bs] * (1.0f / (2.0f * (float)NPTS * 3.0f));
        g_cent[bid][0] = t1;
        g_cent[bid][1] = t2;
        g_cent[bid][2] = t3;
    }
}

__global__ __launch_bounds__(256) void finalize_kernel(float* __restrict__ out)
{
    __shared__ float red0[8];
    __shared__ float red1[8];
    const int tid = threadIdx.x;

    // Sum the chamfer partials (weights already applied).
    float s = 0.0f;
    for (int i = tid; i < NBLK; i += 256) s += g_part[i];

    // Centroid loss: thread t < 48 handles (bs, dim).
    float c = 0.0f;
    if (tid < 48) {
        const int bs = tid / 3, d = tid % 3;
        float sx = 0.0f, st = 0.0f;
        #pragma unroll
        for (int ch = 0; ch < CHUNKS; ch++) {
            sx += g_cent[ch + CHUNKS * bs][d];                   // dir=0 -> X
            st += g_cent[ch + CHUNKS * bs + CHUNKS * BS_][d];    // dir=1 -> T
        }
        c = smooth_l1((sx - st) * (1.0f / (float)NPTS));
    }

    #pragma unroll
    for (int o = 16; o > 0; o >>= 1) {
        s += __shfl_down_sync(0xFFFFFFFFu, s, o);
        c += __shfl_down_sync(0xFFFFFFFFu, c, o);
    }
    if ((tid & 31) == 0) { red0[tid >> 5] = s; red1[tid >> 5] = c; }
    __syncthreads();
    if (tid == 0) {
        float ts = 0, tc = 0;
        #pragma unroll
        for (int w = 0; w < 8; w++) { ts += red0[w]; tc += red1[w]; }
        out[0] = ts;
        out[1] = tc * (1.0f / 6.0f);   // / (B*3)
    }
}

extern "C" void kernel_launch(void* const* d_in, const int* in_sizes, int n_in,
                              void* d_out, int out_size) {
    const float* X = (const float*)d_in[0];   // [B,S,N,3]
    const float* T = (const float*)d_in[1];   // [B,S,N,3]
    const float* W = (const float*)d_in[2];   // [B,S]
    float* out = (float*)d_out;               // [2] -> (loss, lossc)

    dim3 grid(CHUNKS, BS_, 2);
    chamfer_kernel<<<grid, THREADS>>>(X, T, W);
    finalize_kernel<<<1, 256>>>(out);
}